// round 7
// baseline (speedup 1.0000x reference)
#include <cuda_runtime.h>
#include <math.h>

#define BSZ   128
#define TLEN  256
#define NCLS  128
#define WDIM  512
#define UNITS 512
#define JDIM  2048   // 4*UNITS
#define KX    640    // NC+WD (x-part of IN_DIM)

// ---------------- persistent device scratch ------------------------------------------
__device__ float g_Xproj[(size_t)TLEN * BSZ * JDIM];  // [t][b][j] = bias + x@Wx
__device__ float g_h[2][BSZ * UNITS];   // ping-pong h buffers
__device__ float g_c[BSZ * UNITS];      // cell state (owner-block private)
__device__ float g_wsum[JDIM];          // 1e-5 * colsum of word rows of W
__device__ int   g_idx[BSZ];
__device__ int   g_cnt[TLEN * 8];       // per-(step, b-tile) arrival counters

// ---------------- accurate fp32 math independent of -use_fast_math ----------------
__device__ __forceinline__ float my_exp(float x) {
    float t = x * 1.4426950408889634f;
    float n = rintf(t);
    float f = t - n;
    float p =             1.5252733e-5f;
    p = fmaf(p, f, 1.5403530e-4f);
    p = fmaf(p, f, 1.3333558e-3f);
    p = fmaf(p, f, 9.6181291e-3f);
    p = fmaf(p, f, 5.5504109e-2f);
    p = fmaf(p, f, 2.4022647e-1f);
    p = fmaf(p, f, 6.9314718e-1f);
    p = fmaf(p, f, 1.0f);
    return ldexpf(p, (int)n);
}
__device__ __forceinline__ float my_sigmoid(float x) {
    return 1.0f / (1.0f + my_exp(-x));
}
__device__ __forceinline__ float my_tanh(float x) {
    if (x >  20.0f) return  1.0f;
    if (x < -20.0f) return -1.0f;
    float e = my_exp(2.0f * x);
    return (e - 1.0f) / (e + 1.0f);
}

// ---------------- init: zero state + counters (every call: determinism) -------------
__global__ void init_kernel() {
    int i = blockIdx.x * blockDim.x + threadIdx.x;
    if (i < BSZ * UNITS) {
        g_h[0][i] = 0.0f;
        g_h[1][i] = 0.0f;
        g_c[i]    = 0.0f;
    }
    if (i < TLEN * 8) g_cnt[i] = 0;
}

// ---------------- word-row column sums: g_wsum[j] = 1e-5 * sum_r W[640+r][j] -------
__global__ void wsum_kernel(const float* __restrict__ W) {
    int j = blockIdx.x * blockDim.x + threadIdx.x;
    if (j < JDIM) {
        float s = 0.0f;
        for (int r = 0; r < NCLS; ++r) s += W[(size_t)(KX + r) * JDIM + j];
        g_wsum[j] = 1e-5f * s;
    }
}

// ---------------- Xproj[t][b][j] = bias[j] + sum_{k<640} x[t,b,k] * W[k][j] --------
__global__ __launch_bounds__(256) void xproj_kernel(
    const float* __restrict__ xc, const float* __restrict__ xw,
    const float* __restrict__ W, const float* __restrict__ bias)
{
    __shared__ float As[16][128];   // [k][b]
    __shared__ float Bs[16][128];   // [k][n]
    const int t   = blockIdx.y;
    const int n0  = blockIdx.x * 128;
    const int tid = threadIdx.x;
    const int tr  = tid >> 4;
    const int tc  = tid & 15;

    float acc[8][8];
#pragma unroll
    for (int i = 0; i < 8; ++i)
#pragma unroll
        for (int j = 0; j < 8; ++j) acc[i][j] = 0.0f;

    for (int k0 = 0; k0 < KX; k0 += 16) {
        for (int i = tid; i < 512; i += 256) {
            int bb = i >> 2;
            int kq = i & 3;
            int k  = k0 + kq * 4;
            const float* src = (k < NCLS)
                ? (xc + ((size_t)bb * TLEN + t) * NCLS + k)
                : (xw + ((size_t)bb * TLEN + t) * WDIM + (k - NCLS));
            float4 v = *(const float4*)src;
            As[kq*4+0][bb] = v.x;
            As[kq*4+1][bb] = v.y;
            As[kq*4+2][bb] = v.z;
            As[kq*4+3][bb] = v.w;
        }
        for (int i = tid; i < 512; i += 256) {
            int kk = i >> 5;
            int nq = i & 31;
            *(float4*)&Bs[kk][nq*4] =
                *(const float4*)(W + (size_t)(k0+kk)*JDIM + n0 + nq*4);
        }
        __syncthreads();
#pragma unroll
        for (int k = 0; k < 16; ++k) {
            float a[8], b8[8];
#pragma unroll
            for (int i = 0; i < 8; ++i) a[i] = As[k][tr*8 + i];
#pragma unroll
            for (int q = 0; q < 4; ++q) { b8[q] = Bs[k][tc*4 + q]; b8[4+q] = Bs[k][tc*4 + 64 + q]; }
#pragma unroll
            for (int i = 0; i < 8; ++i)
#pragma unroll
                for (int j = 0; j < 8; ++j) acc[i][j] = fmaf(a[i], b8[j], acc[i][j]);
        }
        __syncthreads();
    }
    float bv[8];
#pragma unroll
    for (int q = 0; q < 4; ++q) { bv[q] = bias[n0 + tc*4 + q]; bv[4+q] = bias[n0 + tc*4 + 64 + q]; }
#pragma unroll
    for (int i = 0; i < 8; ++i) {
        int b = tr*8 + i;
        size_t row = ((size_t)t * BSZ + b) * JDIM + n0;
        float4 v0 = make_float4(acc[i][0]+bv[0], acc[i][1]+bv[1], acc[i][2]+bv[2], acc[i][3]+bv[3]);
        float4 v1 = make_float4(acc[i][4]+bv[4], acc[i][5]+bv[5], acc[i][6]+bv[6], acc[i][7]+bv[7]);
        *(float4*)(g_Xproj + row + tc*4)      = v0;
        *(float4*)(g_Xproj + row + tc*4 + 64) = v1;
    }
}

// ---------------- one LSTM time step + fused argmax ----------------------------------
// 128 blocks = 8 b-tiles (16 b) x 16 u-tiles (32 u across 4 gates = 128 U-cols).
// h@U GEMM: 8 chunks of 64 k. Finalize adds precomputed Xproj + word row.
// Then the 4 LAST-ARRIVING blocks of each b-tile (atomic counter) compute
// logits + argmax for 4 batches each. Cross-block h goes through L2
// (__stcg / __threadfence / __ldcg) since L1 is not coherent within a launch.
__global__ __launch_bounds__(256) void step_kernel(
    int t, const float* __restrict__ W, const float* __restrict__ Umat,
    const float* __restrict__ Ws, const float* __restrict__ bsv,
    float* __restrict__ out)
{
    __shared__ float B_s[64][128];    // U chunk / Ws chunk            (32 KB)
    __shared__ float A_s[16][64];     // h chunk / logits scratch      (4 KB)
    __shared__ float zbuf[16][128];   // z tile / h rows for argmax    (8 KB)
    __shared__ int   rank_s;

    const int tid = threadIdx.x;
    const int blk = blockIdx.x;
    const int btile = blk >> 4;
    const int b0  = btile * 16;
    const int u0  = (blk & 15) * 32;
    const float* hin  = g_h[t & 1];
    float*       hout = g_h[(t + 1) & 1];

    const int rg = tid >> 6;
    const int cp = tid & 63;

    float acc[4][2];
#pragma unroll
    for (int r = 0; r < 4; ++r) { acc[r][0] = 0.0f; acc[r][1] = 0.0f; }

    for (int k0 = 0; k0 < UNITS; k0 += 64) {
        for (int i = tid; i < 64 * 32; i += 256) {
            int kk = i >> 5;
            int c  = (i & 31) * 4;
            int g  = c >> 5;
            int uu = c & 31;
            *(float4*)&B_s[kk][c] =
                *(const float4*)(Umat + (size_t)(k0 + kk) * JDIM + g * 512 + u0 + uu);
        }
        {
            int bl = tid >> 4;
            int kq = tid & 15;
            *(float4*)&A_s[bl][kq * 4] =
                *(const float4*)(hin + (size_t)(b0 + bl) * UNITS + k0 + kq * 4);
        }
        __syncthreads();
#pragma unroll 16
        for (int kk = 0; kk < 64; ++kk) {
            float u0v = B_s[kk][cp];
            float u1v = B_s[kk][cp + 64];
#pragma unroll
            for (int r = 0; r < 4; ++r) {
                float av = A_s[rg * 4 + r][kk];
                acc[r][0] = fmaf(av, u0v, acc[r][0]);
                acc[r][1] = fmaf(av, u1v, acc[r][1]);
            }
        }
        __syncthreads();
    }
#pragma unroll
    for (int r = 0; r < 4; ++r) {
        zbuf[rg * 4 + r][cp]      = acc[r][0];
        zbuf[rg * 4 + r][cp + 64] = acc[r][1];
    }
    __syncthreads();

    // ---- finalize: gates + cell update; h -> L2 via stcg ----
    const float* xbase = g_Xproj + (size_t)t * BSZ * JDIM;
#pragma unroll
    for (int q = 0; q < 2; ++q) {
        int p  = tid + q * 256;
        int bl = p >> 5;
        int uu = p & 31;
        int b  = b0 + bl;
        int widx = (t == 0) ? -1 : g_idx[b];
        float z[4];
#pragma unroll
        for (int g = 0; g < 4; ++g) {
            int j = g * 512 + u0 + uu;
            float wrow = (widx < 0) ? g_wsum[j]
                                    : W[(size_t)(KX + widx) * JDIM + j];
            z[g] = zbuf[bl][g * 32 + uu] + xbase[(size_t)b * JDIM + j] + wrow;
        }
        float ig = my_sigmoid(z[0]);
        float fg = my_sigmoid(z[1]);
        float gg = my_tanh(z[2]);
        float og = my_sigmoid(z[3]);
        size_t ci = (size_t)b * UNITS + u0 + uu;
        float cn = fmaf(fg, g_c[ci], ig * gg);
        g_c[ci] = cn;
        __stcg(&hout[ci], og * my_tanh(cn));
    }
    __threadfence();          // h writes visible at L2 before counter bump
    __syncthreads();

    if (tid == 0) rank_s = atomicAdd(&g_cnt[t * 8 + btile], 1);
    __syncthreads();
    int rank = rank_s;
    if (rank < 12) return;    // first 12 arrivals are done

    // wait until all 16 sibling blocks have published h
    if (tid == 0) {
        while (*((volatile int*)&g_cnt[t * 8 + btile]) < 16) { }
    }
    __syncthreads();

    // ---- argmax for 4 batches: bb0 .. bb0+3 ----
    const int bb0 = b0 + (rank - 12) * 4;
    float* hv = &zbuf[0][0];          // 4 x 512 h rows
    for (int j = tid; j < 512; j += 256) {      // float4 units: 4*512/4 = 512
        int b4 = j >> 7;
        float4 v = __ldcg((const float4*)(hout + (size_t)(bb0 + b4) * UNITS + (j & 127) * 4));
        *(float4*)&hv[b4 * 512 + (j & 127) * 4] = v;
    }
    __syncthreads();

    const int m  = tid & 127;
    const int bq = tid >> 7;          // handles batches bq and bq+2
    float a0 = 0.0f, a1 = 0.0f;
    for (int c = 0; c < 8; ++c) {     // Ws chunks of 64k x 128m through B_s
        for (int i = tid; i < 2048; i += 256) {   // float4 units
            int kk = i >> 5;
            int nq = (i & 31) * 4;
            *(float4*)&B_s[kk][nq] =
                *(const float4*)(Ws + (size_t)(c * 64 + kk) * NCLS + nq);
        }
        __syncthreads();
#pragma unroll 16
        for (int kk = 0; kk < 64; ++kk) {
            float ws = B_s[kk][m];
            a0 = fmaf(hv[bq * 512 + c * 64 + kk],       ws, a0);
            a1 = fmaf(hv[(bq + 2) * 512 + c * 64 + kk], ws, a1);
        }
        __syncthreads();
    }
    float* lg = &A_s[0][0];           // 4 x 128 logits
    float bsm = bsv[m];
    lg[bq * 128 + m]       = a0 + bsm;
    lg[(bq + 2) * 128 + m] = a1 + bsm;
    __syncthreads();

    if (tid < 128) {                  // warp w handles batch bb0 + w
        int w    = tid >> 5;
        int lane = tid & 31;
        float bv = -INFINITY; int bi = 0x7fffffff;
        for (int mm = lane; mm < 128; mm += 32) {
            float v = lg[w * 128 + mm];
            if (v > bv) { bv = v; bi = mm; }      // ascending -> first max kept
        }
#pragma unroll
        for (int off = 16; off > 0; off >>= 1) {
            float ov = __shfl_down_sync(0xffffffffu, bv, off);
            int   oi = __shfl_down_sync(0xffffffffu, bi, off);
            if (ov > bv || (ov == bv && oi < bi)) { bv = ov; bi = oi; }
        }
        if (lane == 0) {
            int b = bb0 + w;
            g_idx[b] = bi;                        // consumed next launch
            out[(size_t)b * TLEN + t] = (float)bi;
        }
    }
}

// ---------------- harness entry ------------------------------------------------------
extern "C" void kernel_launch(void* const* d_in, const int* in_sizes, int n_in,
                              void* d_out, int out_size) {
    (void)out_size;
    const float *xc = 0, *xw = 0, *W = 0, *U = 0, *bb = 0, *Ws = 0, *bs = 0;
    for (int i = 0; i < n_in; ++i) {
        switch (in_sizes[i]) {
            case BSZ*TLEN*NCLS:   xc = (const float*)d_in[i]; break;
            case BSZ*TLEN*WDIM:   xw = (const float*)d_in[i]; break;
            case (KX+NCLS)*JDIM:  W  = (const float*)d_in[i]; break;
            case UNITS*JDIM:      U  = (const float*)d_in[i]; break;
            case JDIM:            bb = (const float*)d_in[i]; break;
            case UNITS*NCLS:      Ws = (const float*)d_in[i]; break;
            case NCLS:            bs = (const float*)d_in[i]; break;
            default: break;
        }
    }
    if (!xc || !xw || !W || !U || !bb || !Ws || !bs) {
        xc = (const float*)d_in[0]; xw = (const float*)d_in[1];
        W  = (const float*)d_in[2]; U  = (const float*)d_in[3];
        bb = (const float*)d_in[4]; Ws = (const float*)d_in[5];
        bs = (const float*)d_in[6];
    }
    float* out = (float*)d_out;                // [128,256] as float32

    init_kernel<<<(BSZ*UNITS + 255) / 256, 256>>>();
    wsum_kernel<<<(JDIM + 255) / 256, 256>>>(W);
    dim3 gx(JDIM / 128, TLEN);
    xproj_kernel<<<gx, 256>>>(xc, xw, W, bb);
    for (int t = 0; t < TLEN; ++t) {
        step_kernel<<<128, 256>>>(t, W, U, Ws, bs, out);
    }
}

// round 10
// speedup vs baseline: 1.3857x; 1.3857x over previous
#include <cuda_runtime.h>
#include <math.h>

#define BSZ   128
#define TLEN  256
#define NCLS  128
#define WDIM  512
#define UNITS 512
#define JDIM  2048   // 4*UNITS
#define KX    640    // NC+WD (x-part of IN_DIM)

// ---------------- persistent device scratch ------------------------------------------
__device__ float g_Xproj[(size_t)TLEN * BSZ * JDIM];  // [t][b][j] = bias + x@Wx
__device__ float g_h[2][BSZ * UNITS];   // ping-pong h buffers, layout [b][unit]
__device__ float g_c[BSZ * UNITS];      // cell state (owner-block private)
__device__ float g_wsum[JDIM];          // 1e-5 * colsum of word rows of W
__device__ int   g_idx[BSZ];

// ---------------- accurate fp32 math independent of -use_fast_math ----------------
__device__ __forceinline__ float my_exp(float x) {
    float t = x * 1.4426950408889634f;
    float n = rintf(t);
    float f = t - n;
    float p =             1.5252733e-5f;
    p = fmaf(p, f, 1.5403530e-4f);
    p = fmaf(p, f, 1.3333558e-3f);
    p = fmaf(p, f, 9.6181291e-3f);
    p = fmaf(p, f, 5.5504109e-2f);
    p = fmaf(p, f, 2.4022647e-1f);
    p = fmaf(p, f, 6.9314718e-1f);
    p = fmaf(p, f, 1.0f);
    return ldexpf(p, (int)n);
}
__device__ __forceinline__ float my_sigmoid(float x) {
    return 1.0f / (1.0f + my_exp(-x));
}
__device__ __forceinline__ float my_tanh(float x) {
    if (x >  20.0f) return  1.0f;
    if (x < -20.0f) return -1.0f;
    float e = my_exp(2.0f * x);
    return (e - 1.0f) / (e + 1.0f);
}

// ---------------- init: zero h buffers and cell state (every call) ------------------
__global__ void init_kernel() {
    int i = blockIdx.x * blockDim.x + threadIdx.x;
    if (i < BSZ * UNITS) {
        g_h[0][i] = 0.0f;
        g_h[1][i] = 0.0f;
        g_c[i]    = 0.0f;
    }
}

// ---------------- word-row column sums -------------------------------------------------
__global__ void wsum_kernel(const float* __restrict__ W) {
    int j = blockIdx.x * blockDim.x + threadIdx.x;
    if (j < JDIM) {
        float s = 0.0f;
        for (int r = 0; r < NCLS; ++r) s += W[(size_t)(KX + r) * JDIM + j];
        g_wsum[j] = 1e-5f * s;
    }
}

// ---------------- Xproj[t][b][j] = bias[j] + sum_{k<640} x[t,b,k] * W[k][j] ----------
// (verbatim from passing rounds 6/7)
__global__ __launch_bounds__(256) void xproj_kernel(
    const float* __restrict__ xc, const float* __restrict__ xw,
    const float* __restrict__ W, const float* __restrict__ bias)
{
    __shared__ float As[16][128];
    __shared__ float Bs[16][128];
    const int t   = blockIdx.y;
    const int n0  = blockIdx.x * 128;
    const int tid = threadIdx.x;
    const int tr  = tid >> 4;
    const int tc  = tid & 15;

    float acc[8][8];
#pragma unroll
    for (int i = 0; i < 8; ++i)
#pragma unroll
        for (int j = 0; j < 8; ++j) acc[i][j] = 0.0f;

    for (int k0 = 0; k0 < KX; k0 += 16) {
        for (int i = tid; i < 512; i += 256) {
            int bb = i >> 2;
            int kq = i & 3;
            int k  = k0 + kq * 4;
            const float* src = (k < NCLS)
                ? (xc + ((size_t)bb * TLEN + t) * NCLS + k)
                : (xw + ((size_t)bb * TLEN + t) * WDIM + (k - NCLS));
            float4 v = *(const float4*)src;
            As[kq*4+0][bb] = v.x;
            As[kq*4+1][bb] = v.y;
            As[kq*4+2][bb] = v.z;
            As[kq*4+3][bb] = v.w;
        }
        for (int i = tid; i < 512; i += 256) {
            int kk = i >> 5;
            int nq = i & 31;
            *(float4*)&Bs[kk][nq*4] =
                *(const float4*)(W + (size_t)(k0+kk)*JDIM + n0 + nq*4);
        }
        __syncthreads();
#pragma unroll
        for (int k = 0; k < 16; ++k) {
            float a[8], b8[8];
#pragma unroll
            for (int i = 0; i < 8; ++i) a[i] = As[k][tr*8 + i];
#pragma unroll
            for (int q = 0; q < 4; ++q) { b8[q] = Bs[k][tc*4 + q]; b8[4+q] = Bs[k][tc*4 + 64 + q]; }
#pragma unroll
            for (int i = 0; i < 8; ++i)
#pragma unroll
                for (int j = 0; j < 8; ++j) acc[i][j] = fmaf(a[i], b8[j], acc[i][j]);
        }
        __syncthreads();
    }
    float bv[8];
#pragma unroll
    for (int q = 0; q < 4; ++q) { bv[q] = bias[n0 + tc*4 + q]; bv[4+q] = bias[n0 + tc*4 + 64 + q]; }
#pragma unroll
    for (int i = 0; i < 8; ++i) {
        int b = tr*8 + i;
        size_t row = ((size_t)t * BSZ + b) * JDIM + n0;
        float4 v0 = make_float4(acc[i][0]+bv[0], acc[i][1]+bv[1], acc[i][2]+bv[2], acc[i][3]+bv[3]);
        float4 v1 = make_float4(acc[i][4]+bv[4], acc[i][5]+bv[5], acc[i][6]+bv[6], acc[i][7]+bv[7]);
        *(float4*)(g_Xproj + row + tc*4)      = v0;
        *(float4*)(g_Xproj + row + tc*4 + 64) = v1;
    }
}

// ---------------- one LSTM time step (h@U only, Xproj precomputed) -------------------
// Verbatim the PASSING round-7 step_kernel, with the fused-argmax tail removed and
// plain stores for hout (cross-launch coherence via launch boundary, as in round 6).
__global__ __launch_bounds__(256) void step_kernel(
    int t, const float* __restrict__ W, const float* __restrict__ Umat)
{
    __shared__ float B_s[64][128];
    __shared__ float A_s[16][64];
    __shared__ float zbuf[16][128];

    const int tid = threadIdx.x;
    const int blk = blockIdx.x;
    const int b0  = (blk >> 4) * 16;
    const int u0  = (blk & 15) * 32;
    const float* hin  = g_h[t & 1];
    float*       hout = g_h[(t + 1) & 1];

    const int rg = tid >> 6;
    const int cp = tid & 63;

    float acc[4][2];
#pragma unroll
    for (int r = 0; r < 4; ++r) { acc[r][0] = 0.0f; acc[r][1] = 0.0f; }

    for (int k0 = 0; k0 < UNITS; k0 += 64) {
        for (int i = tid; i < 64 * 32; i += 256) {
            int kk = i >> 5;
            int c  = (i & 31) * 4;
            int g  = c >> 5;
            int uu = c & 31;
            *(float4*)&B_s[kk][c] =
                *(const float4*)(Umat + (size_t)(k0 + kk) * JDIM + g * 512 + u0 + uu);
        }
        {
            int bl = tid >> 4;
            int kq = tid & 15;
            *(float4*)&A_s[bl][kq * 4] =
                *(const float4*)(hin + (size_t)(b0 + bl) * UNITS + k0 + kq * 4);
        }
        __syncthreads();
#pragma unroll 16
        for (int kk = 0; kk < 64; ++kk) {
            float u0v = B_s[kk][cp];
            float u1v = B_s[kk][cp + 64];
#pragma unroll
            for (int r = 0; r < 4; ++r) {
                float av = A_s[rg * 4 + r][kk];
                acc[r][0] = fmaf(av, u0v, acc[r][0]);
                acc[r][1] = fmaf(av, u1v, acc[r][1]);
            }
        }
        __syncthreads();
    }
#pragma unroll
    for (int r = 0; r < 4; ++r) {
        zbuf[rg * 4 + r][cp]      = acc[r][0];
        zbuf[rg * 4 + r][cp + 64] = acc[r][1];
    }
    __syncthreads();

    const float* xbase = g_Xproj + (size_t)t * BSZ * JDIM;
#pragma unroll
    for (int q = 0; q < 2; ++q) {
        int p  = tid + q * 256;
        int bl = p >> 5;
        int uu = p & 31;
        int b  = b0 + bl;
        int widx = (t == 0) ? -1 : g_idx[b];
        float z[4];
#pragma unroll
        for (int g = 0; g < 4; ++g) {
            int j = g * 512 + u0 + uu;
            float wrow = (widx < 0) ? g_wsum[j]
                                    : W[(size_t)(KX + widx) * JDIM + j];
            z[g] = zbuf[bl][g * 32 + uu] + xbase[(size_t)b * JDIM + j] + wrow;
        }
        float ig = my_sigmoid(z[0]);
        float fg = my_sigmoid(z[1]);
        float gg = my_tanh(z[2]);
        float og = my_sigmoid(z[3]);
        size_t ci = (size_t)b * UNITS + u0 + uu;
        float cn = fmaf(fg, g_c[ci], ig * gg);
        g_c[ci] = cn;
        hout[ci] = og * my_tanh(cn);
    }
}

// ---------------- logits + argmax, 8 batches per block -------------------------------
// grid 16. Ws staged through smem in 8 chunks (coalesced float4); thread handles
// 1 batch x 4 class-columns -> 2048 FMA/thread, LDS-friendly (Ws float4, h broadcast).
#define AM_SMEM_FLOATS (8*512 + 64*128 + 8*128)   // hs + wsch + lg
#define AM_SMEM_BYTES  (AM_SMEM_FLOATS * 4)

__global__ __launch_bounds__(256) void argmax_kernel(
    int t, const float* __restrict__ Ws, const float* __restrict__ bsv,
    float* __restrict__ out)
{
    extern __shared__ float sm[];
    float* hs   = sm;                       // [8][512]
    float* wsch = sm + 8*512;               // [64][128]
    float* lg   = sm + 8*512 + 64*128;      // [8][128]

    const int tid = threadIdx.x;
    const int b0  = blockIdx.x * 8;
    const float* hbuf = g_h[(t + 1) & 1];

    // load 8 h rows (1024 float4)
    for (int it = 0; it < 4; ++it) {
        int idx = tid + it * 256;
        int bb  = idx >> 7;
        int kq  = (idx & 127) * 4;
        *(float4*)&hs[bb * 512 + kq] =
            *(const float4*)(hbuf + (size_t)(b0 + bb) * UNITS + kq);
    }
    __syncthreads();

    const int m4 = (tid & 31) * 4;    // 4 class columns
    const int bq = tid >> 5;          // batch 0..7
    float acc0 = 0.0f, acc1 = 0.0f, acc2 = 0.0f, acc3 = 0.0f;

    for (int c = 0; c < 8; ++c) {
        for (int it = 0; it < 8; ++it) {          // 2048 float4 = 64k x 128m
            int idx = tid + it * 256;
            int kk  = idx >> 5;
            int mq  = (idx & 31) * 4;
            *(float4*)&wsch[kk * 128 + mq] =
                *(const float4*)(Ws + (size_t)(c * 64 + kk) * NCLS + mq);
        }
        __syncthreads();
        const float* hrow = &hs[bq * 512 + c * 64];
#pragma unroll 16
        for (int kk = 0; kk < 64; ++kk) {
            float  hv = hrow[kk];                  // warp-broadcast
            float4 w4 = *(const float4*)&wsch[kk * 128 + m4];
            acc0 = fmaf(hv, w4.x, acc0);
            acc1 = fmaf(hv, w4.y, acc1);
            acc2 = fmaf(hv, w4.z, acc2);
            acc3 = fmaf(hv, w4.w, acc3);
        }
        __syncthreads();
    }
    {
        float4 bsq = *(const float4*)(bsv + m4);
        lg[bq * 128 + m4 + 0] = acc0 + bsq.x;
        lg[bq * 128 + m4 + 1] = acc1 + bsq.y;
        lg[bq * 128 + m4 + 2] = acc2 + bsq.z;
        lg[bq * 128 + m4 + 3] = acc3 + bsq.w;
    }
    __syncthreads();

    // warp w -> batch b0 + w (ascending scan, strict > => first-index tie-break)
    {
        int w    = tid >> 5;
        int lane = tid & 31;
        float bv = -INFINITY; int bi = 0x7fffffff;
        for (int mm = lane; mm < 128; mm += 32) {
            float v = lg[w * 128 + mm];
            if (v > bv) { bv = v; bi = mm; }
        }
#pragma unroll
        for (int off = 16; off > 0; off >>= 1) {
            float ov = __shfl_down_sync(0xffffffffu, bv, off);
            int   oi = __shfl_down_sync(0xffffffffu, bi, off);
            if (ov > bv || (ov == bv && oi < bi)) { bv = ov; bi = oi; }
        }
        if (lane == 0) {
            int b = b0 + w;
            g_idx[b] = bi;
            out[(size_t)b * TLEN + t] = (float)bi;   // float32 output
        }
    }
}

// ---------------- harness entry ------------------------------------------------------
extern "C" void kernel_launch(void* const* d_in, const int* in_sizes, int n_in,
                              void* d_out, int out_size) {
    (void)out_size;
    const float *xc = 0, *xw = 0, *W = 0, *U = 0, *bb = 0, *Ws = 0, *bs = 0;
    for (int i = 0; i < n_in; ++i) {
        switch (in_sizes[i]) {
            case BSZ*TLEN*NCLS:   xc = (const float*)d_in[i]; break;
            case BSZ*TLEN*WDIM:   xw = (const float*)d_in[i]; break;
            case (KX+NCLS)*JDIM:  W  = (const float*)d_in[i]; break;
            case UNITS*JDIM:      U  = (const float*)d_in[i]; break;
            case JDIM:            bb = (const float*)d_in[i]; break;
            case UNITS*NCLS:      Ws = (const float*)d_in[i]; break;
            case NCLS:            bs = (const float*)d_in[i]; break;
            default: break;
        }
    }
    if (!xc || !xw || !W || !U || !bb || !Ws || !bs) {
        xc = (const float*)d_in[0]; xw = (const float*)d_in[1];
        W  = (const float*)d_in[2]; U  = (const float*)d_in[3];
        bb = (const float*)d_in[4]; Ws = (const float*)d_in[5];
        bs = (const float*)d_in[6];
    }
    float* out = (float*)d_out;                // [128,256] as float32

    cudaFuncSetAttribute(argmax_kernel,
                         cudaFuncAttributeMaxDynamicSharedMemorySize, AM_SMEM_BYTES);

    init_kernel<<<(BSZ*UNITS + 255) / 256, 256>>>();
    wsum_kernel<<<(JDIM + 255) / 256, 256>>>(W);
    dim3 gx(JDIM / 128, TLEN);
    xproj_kernel<<<gx, 256>>>(xc, xw, W, bb);
    for (int t = 0; t < TLEN; ++t) {
        step_kernel<<<128, 256>>>(t, W, U);
        argmax_kernel<<<16, 256, AM_SMEM_BYTES>>>(t, Ws, bs, out);
    }
}

// round 13
// speedup vs baseline: 2.2920x; 1.6540x over previous
#include <cuda_runtime.h>
#include <math.h>
#include <stdint.h>

#define BSZ   128
#define TLEN  256
#define NCLS  128
#define WDIM  512
#define UNITS 512
#define JDIM  2048   // 4*UNITS
#define KX    640    // NC+WD (x-part of IN_DIM)

// ---------------- persistent device scratch ------------------------------------------
__device__ float g_Xproj[(size_t)TLEN * BSZ * JDIM];  // [t][b][j] = bias + x@Wx
__device__ float g_h[2][BSZ * UNITS];   // ping-pong h buffers, layout [b][unit]
__device__ float g_c[BSZ * UNITS];      // cell state (owner-block private)
__device__ float g_wsum[JDIM];          // 1e-5 * colsum of word rows of W
__device__ float g_part[BSZ * 16 * NCLS]; // partial logits [b][ut][m]
__device__ int   g_idx[BSZ];

// ---------------- accurate fp32 math independent of -use_fast_math ----------------
__device__ __forceinline__ float my_exp(float x) {
    float t = x * 1.4426950408889634f;
    float n = rintf(t);
    float f = t - n;
    float p =             1.5252733e-5f;
    p = fmaf(p, f, 1.5403530e-4f);
    p = fmaf(p, f, 1.3333558e-3f);
    p = fmaf(p, f, 9.6181291e-3f);
    p = fmaf(p, f, 5.5504109e-2f);
    p = fmaf(p, f, 2.4022647e-1f);
    p = fmaf(p, f, 6.9314718e-1f);
    p = fmaf(p, f, 1.0f);
    return ldexpf(p, (int)n);
}
__device__ __forceinline__ float my_sigmoid(float x) {
    return 1.0f / (1.0f + my_exp(-x));
}
__device__ __forceinline__ float my_tanh(float x) {
    if (x >  20.0f) return  1.0f;
    if (x < -20.0f) return -1.0f;
    float e = my_exp(2.0f * x);
    return (e - 1.0f) / (e + 1.0f);
}

// ---------------- cp.async helpers ----------------------------------------------------
__device__ __forceinline__ uint32_t smem_u32(const void* p) {
    uint32_t a;
    asm("{ .reg .u64 t; cvta.to.shared.u64 t, %1; cvt.u32.u64 %0, t; }"
        : "=r"(a) : "l"(p));
    return a;
}
__device__ __forceinline__ void cp_async16(uint32_t dst, const void* src) {
    asm volatile("cp.async.cg.shared.global [%0], [%1], 16;" :: "r"(dst), "l"(src));
}
__device__ __forceinline__ void cp_commit() {
    asm volatile("cp.async.commit_group;");
}
__device__ __forceinline__ void cp_wait1() {
    asm volatile("cp.async.wait_group 1;");
}
__device__ __forceinline__ void cp_wait0() {
    asm volatile("cp.async.wait_group 0;");
}

// ---------------- init ----------------------------------------------------------------
__global__ void init_kernel() {
    int i = blockIdx.x * blockDim.x + threadIdx.x;
    if (i < BSZ * UNITS) {
        g_h[0][i] = 0.0f;
        g_h[1][i] = 0.0f;
        g_c[i]    = 0.0f;
    }
}

// ---------------- word-row column sums -------------------------------------------------
__global__ void wsum_kernel(const float* __restrict__ W) {
    int j = blockIdx.x * blockDim.x + threadIdx.x;
    if (j < JDIM) {
        float s = 0.0f;
        for (int r = 0; r < NCLS; ++r) s += W[(size_t)(KX + r) * JDIM + j];
        g_wsum[j] = 1e-5f * s;
    }
}

// ---------------- Xproj[t][b][j] = bias[j] + sum_{k<640} x[t,b,k] * W[k][j] ----------
// (verbatim from passing rounds)
__global__ __launch_bounds__(256) void xproj_kernel(
    const float* __restrict__ xc, const float* __restrict__ xw,
    const float* __restrict__ W, const float* __restrict__ bias)
{
    __shared__ float As[16][128];
    __shared__ float Bs[16][128];
    const int t   = blockIdx.y;
    const int n0  = blockIdx.x * 128;
    const int tid = threadIdx.x;
    const int tr  = tid >> 4;
    const int tc  = tid & 15;

    float acc[8][8];
#pragma unroll
    for (int i = 0; i < 8; ++i)
#pragma unroll
        for (int j = 0; j < 8; ++j) acc[i][j] = 0.0f;

    for (int k0 = 0; k0 < KX; k0 += 16) {
        for (int i = tid; i < 512; i += 256) {
            int bb = i >> 2;
            int kq = i & 3;
            int k  = k0 + kq * 4;
            const float* src = (k < NCLS)
                ? (xc + ((size_t)bb * TLEN + t) * NCLS + k)
                : (xw + ((size_t)bb * TLEN + t) * WDIM + (k - NCLS));
            float4 v = *(const float4*)src;
            As[kq*4+0][bb] = v.x;
            As[kq*4+1][bb] = v.y;
            As[kq*4+2][bb] = v.z;
            As[kq*4+3][bb] = v.w;
        }
        for (int i = tid; i < 512; i += 256) {
            int kk = i >> 5;
            int nq = i & 31;
            *(float4*)&Bs[kk][nq*4] =
                *(const float4*)(W + (size_t)(k0+kk)*JDIM + n0 + nq*4);
        }
        __syncthreads();
#pragma unroll
        for (int k = 0; k < 16; ++k) {
            float a[8], b8[8];
#pragma unroll
            for (int i = 0; i < 8; ++i) a[i] = As[k][tr*8 + i];
#pragma unroll
            for (int q = 0; q < 4; ++q) { b8[q] = Bs[k][tc*4 + q]; b8[4+q] = Bs[k][tc*4 + 64 + q]; }
#pragma unroll
            for (int i = 0; i < 8; ++i)
#pragma unroll
                for (int j = 0; j < 8; ++j) acc[i][j] = fmaf(a[i], b8[j], acc[i][j]);
        }
        __syncthreads();
    }
    float bv[8];
#pragma unroll
    for (int q = 0; q < 4; ++q) { bv[q] = bias[n0 + tc*4 + q]; bv[4+q] = bias[n0 + tc*4 + 64 + q]; }
#pragma unroll
    for (int i = 0; i < 8; ++i) {
        int b = tr*8 + i;
        size_t row = ((size_t)t * BSZ + b) * JDIM + n0;
        float4 v0 = make_float4(acc[i][0]+bv[0], acc[i][1]+bv[1], acc[i][2]+bv[2], acc[i][3]+bv[3]);
        float4 v1 = make_float4(acc[i][4]+bv[4], acc[i][5]+bv[5], acc[i][6]+bv[6], acc[i][7]+bv[7]);
        *(float4*)(g_Xproj + row + tc*4)      = v0;
        *(float4*)(g_Xproj + row + tc*4 + 64) = v1;
    }
}

// ---------------- smem layout for step kernel (floats) -------------------------------
#define SOF_B    0          // [2][64][128] U chunks (double buffer)   16384
#define SOF_A    16384      // [2][16][64]  h chunks (double buffer)    2048
#define SOF_Z    18432      // [16][128]    z tile                      2048
#define SOF_WSL  20480      // [32][128]    Ws slice                    4096
#define SOF_HN   24576      // [16][32]     h_new tile                   512
#define STEP_SMEM_FLOATS 25088
#define STEP_SMEM_BYTES  (STEP_SMEM_FLOATS * 4)

// ---------------- one LSTM time step + partial logits --------------------------------
// Same tiling/math as the PASSING round-10 step (128 blocks = 8 b-tiles x 16 u-tiles),
// but with cp.async double-buffered loads (latency hiding) and a cheap fused
// partial-logit stage: g_part[b][ut][m] = sum_{uu<32} h_new[b][u0+uu] * Ws[u0+uu][m].
__global__ __launch_bounds__(256) void step_kernel(
    int t, const float* __restrict__ W, const float* __restrict__ Umat,
    const float* __restrict__ Ws)
{
    extern __shared__ float sm[];
    float* B_s  = sm + SOF_B;
    float* A_s  = sm + SOF_A;
    float* zbuf = sm + SOF_Z;
    float* Wsl  = sm + SOF_WSL;
    float* hn   = sm + SOF_HN;

    const int tid = threadIdx.x;
    const int blk = blockIdx.x;
    const int b0  = (blk >> 4) * 16;
    const int ut  = blk & 15;
    const int u0  = ut * 32;
    const float* hin  = g_h[t & 1];
    float*       hout = g_h[(t + 1) & 1];

    const int rg = tid >> 6;
    const int cp = tid & 63;
    const uint32_t sb = smem_u32(sm);

    // ---- prefetch: Ws slice + chunk 0 (group 0) ----
    for (int it = 0; it < 4; ++it) {                 // Wsl: 1024 float4
        int idx = tid + it * 256;
        int uu  = idx >> 5;
        int mq  = (idx & 31) * 4;
        cp_async16(sb + (uint32_t)((SOF_WSL + uu * 128 + mq) * 4),
                   Ws + (size_t)(u0 + uu) * NCLS + mq);
    }
    {   // chunk 0 into buffer 0
        for (int it = 0; it < 8; ++it) {             // B: 2048 float4
            int idx = tid + it * 256;
            int kk  = idx >> 5;
            int c   = (idx & 31) * 4;
            int g   = c >> 5;
            int uu  = c & 31;
            cp_async16(sb + (uint32_t)((SOF_B + kk * 128 + c) * 4),
                       Umat + (size_t)kk * JDIM + g * 512 + u0 + uu);
        }
        int bl = tid >> 4;
        int kq = tid & 15;
        cp_async16(sb + (uint32_t)((SOF_A + bl * 64 + kq * 4) * 4),
                   hin + (size_t)(b0 + bl) * UNITS + kq * 4);
    }
    cp_commit();

    float acc[4][2];
#pragma unroll
    for (int r = 0; r < 4; ++r) { acc[r][0] = 0.0f; acc[r][1] = 0.0f; }

#pragma unroll
    for (int kc = 0; kc < 8; ++kc) {
        if (kc < 7) {
            int nc  = kc + 1;
            int buf = nc & 1;
            for (int it = 0; it < 8; ++it) {
                int idx = tid + it * 256;
                int kk  = idx >> 5;
                int c   = (idx & 31) * 4;
                int g   = c >> 5;
                int uu  = c & 31;
                cp_async16(sb + (uint32_t)((SOF_B + buf * 8192 + kk * 128 + c) * 4),
                           Umat + (size_t)(nc * 64 + kk) * JDIM + g * 512 + u0 + uu);
            }
            int bl = tid >> 4;
            int kq = tid & 15;
            cp_async16(sb + (uint32_t)((SOF_A + buf * 1024 + bl * 64 + kq * 4) * 4),
                       hin + (size_t)(b0 + bl) * UNITS + nc * 64 + kq * 4);
            cp_commit();
            cp_wait1();
        } else {
            cp_wait0();
        }
        __syncthreads();
        const float* Bb = B_s + (kc & 1) * 8192;
        const float* Ab = A_s + (kc & 1) * 1024;
#pragma unroll 16
        for (int kk = 0; kk < 64; ++kk) {
            float u0v = Bb[kk * 128 + cp];
            float u1v = Bb[kk * 128 + cp + 64];
#pragma unroll
            for (int r = 0; r < 4; ++r) {
                float av = Ab[(rg * 4 + r) * 64 + kk];
                acc[r][0] = fmaf(av, u0v, acc[r][0]);
                acc[r][1] = fmaf(av, u1v, acc[r][1]);
            }
        }
        __syncthreads();
    }
#pragma unroll
    for (int r = 0; r < 4; ++r) {
        zbuf[(rg * 4 + r) * 128 + cp]      = acc[r][0];
        zbuf[(rg * 4 + r) * 128 + cp + 64] = acc[r][1];
    }
    __syncthreads();

    // ---- finalize: gates + cell update (identical math to passing round 10) ----
    const float* xbase = g_Xproj + (size_t)t * BSZ * JDIM;
#pragma unroll
    for (int q = 0; q < 2; ++q) {
        int p  = tid + q * 256;
        int bl = p >> 5;
        int uu = p & 31;
        int b  = b0 + bl;
        int widx = (t == 0) ? -1 : g_idx[b];
        float z[4];
#pragma unroll
        for (int g = 0; g < 4; ++g) {
            int j = g * 512 + u0 + uu;
            float wrow = (widx < 0) ? g_wsum[j]
                                    : W[(size_t)(KX + widx) * JDIM + j];
            z[g] = zbuf[bl * 128 + g * 32 + uu] + xbase[(size_t)b * JDIM + j] + wrow;
        }
        float ig = my_sigmoid(z[0]);
        float fg = my_sigmoid(z[1]);
        float gg = my_tanh(z[2]);
        float og = my_sigmoid(z[3]);
        size_t ci = (size_t)b * UNITS + u0 + uu;
        float cn = fmaf(fg, g_c[ci], ig * gg);
        g_c[ci] = cn;
        float hv = og * my_tanh(cn);
        g_c[ci] = cn;
        hout[ci] = hv;
        hn[bl * 32 + uu] = hv;
    }
    __syncthreads();

    // ---- partial logits for this u-slice: g_part[b][ut][m] ----
    {
        int m  = tid & 127;
        int bh = tid >> 7;            // 0 or 1 -> batches bh*8 .. bh*8+7
        float pacc[8];
#pragma unroll
        for (int r = 0; r < 8; ++r) pacc[r] = 0.0f;
#pragma unroll 8
        for (int uu = 0; uu < 32; ++uu) {
            float wv = Wsl[uu * 128 + m];
#pragma unroll
            for (int r = 0; r < 8; ++r)
                pacc[r] = fmaf(hn[(bh * 8 + r) * 32 + uu], wv, pacc[r]);
        }
#pragma unroll
        for (int r = 0; r < 8; ++r) {
            int b = b0 + bh * 8 + r;
            g_part[(size_t)b * (16 * NCLS) + ut * NCLS + m] = pacc[r];
        }
    }
}

// ---------------- sum partials + argmax (one block per batch) ------------------------
__global__ __launch_bounds__(128) void argmax2_kernel(
    int t, const float* __restrict__ bsv, float* __restrict__ out)
{
    __shared__ float lg[NCLS];
    const int b   = blockIdx.x;
    const int tid = threadIdx.x;    // = class m

    float s = 0.0f;
    const float* pb = g_part + (size_t)b * (16 * NCLS);
#pragma unroll
    for (int utl = 0; utl < 16; ++utl)
        s += pb[utl * NCLS + tid];
    lg[tid] = s + bsv[tid];
    __syncthreads();

    if (tid < 32) {
        float bv = -INFINITY; int bi = 0x7fffffff;
        for (int mm = tid; mm < 128; mm += 32) {
            float v = lg[mm];
            if (v > bv) { bv = v; bi = mm; }   // ascending -> first index kept
        }
#pragma unroll
        for (int off = 16; off > 0; off >>= 1) {
            float ov = __shfl_down_sync(0xffffffffu, bv, off);
            int   oi = __shfl_down_sync(0xffffffffu, bi, off);
            if (ov > bv || (ov == bv && oi < bi)) { bv = ov; bi = oi; }
        }
        if (tid == 0) {
            g_idx[b] = bi;
            out[(size_t)b * TLEN + t] = (float)bi;   // float32 output
        }
    }
}

// ---------------- harness entry ------------------------------------------------------
extern "C" void kernel_launch(void* const* d_in, const int* in_sizes, int n_in,
                              void* d_out, int out_size) {
    (void)out_size;
    const float *xc = 0, *xw = 0, *W = 0, *U = 0, *bb = 0, *Ws = 0, *bs = 0;
    for (int i = 0; i < n_in; ++i) {
        switch (in_sizes[i]) {
            case BSZ*TLEN*NCLS:   xc = (const float*)d_in[i]; break;
            case BSZ*TLEN*WDIM:   xw = (const float*)d_in[i]; break;
            case (KX+NCLS)*JDIM:  W  = (const float*)d_in[i]; break;
            case UNITS*JDIM:      U  = (const float*)d_in[i]; break;
            case JDIM:            bb = (const float*)d_in[i]; break;
            case UNITS*NCLS:      Ws = (const float*)d_in[i]; break;
            case NCLS:            bs = (const float*)d_in[i]; break;
            default: break;
        }
    }
    if (!xc || !xw || !W || !U || !bb || !Ws || !bs) {
        xc = (const float*)d_in[0]; xw = (const float*)d_in[1];
        W  = (const float*)d_in[2]; U  = (const float*)d_in[3];
        bb = (const float*)d_in[4]; Ws = (const float*)d_in[5];
        bs = (const float*)d_in[6];
    }
    float* out = (float*)d_out;                // [128,256] as float32

    cudaFuncSetAttribute(step_kernel,
                         cudaFuncAttributeMaxDynamicSharedMemorySize, STEP_SMEM_BYTES);

    init_kernel<<<(BSZ*UNITS + 255) / 256, 256>>>();
    wsum_kernel<<<(JDIM + 255) / 256, 256>>>(W);
    dim3 gx(JDIM / 128, TLEN);
    xproj_kernel<<<gx, 256>>>(xc, xw, W, bb);
    for (int t = 0; t < TLEN; ++t) {
        step_kernel<<<128, 256, STEP_SMEM_BYTES>>>(t, W, U, Ws);
        argmax2_kernel<<<128, 128>>>(t, bs, out);
    }
}